// round 1
// baseline (speedup 1.0000x reference)
#include <cuda_runtime.h>
#include <cuda_bf16.h>
#include <cstdint>

#define N_NODES 100000
#define N_EDGES 1600000
#define FDIM    128
#define HEADS   8
#define EPS_F   1e-12f
#define ALPHA_F 0.2f

// Scratch (static device globals — no allocation at runtime).
// g_sc[n*16 + h]      : h<8 -> s_src[n][h], h>=8 -> s_dst[n][h-8]   (6.4 MB, L2-resident)
// g_ssum[n*8 + h]     : per-(node,head) sum of exp(e)               (3.2 MB)
__device__ __align__(16) float g_sc[N_NODES * 16];
__device__ __align__(16) float g_ssum[N_NODES * 8];

// ---------------------------------------------------------------------------
// Kernel 1: per-node scores  s_src = x @ a_src^T, s_dst = x @ a_dst^T
// One warp per node. Also zero-initializes g_ssum for that node (fused init so
// the graph stays 3 kernel nodes and replays are self-consistent).
// ---------------------------------------------------------------------------
__global__ void scores_kernel(const float* __restrict__ x,
                              const float* __restrict__ aa,
                              int n_nodes)
{
    __shared__ float sh_aa[HEADS * 2 * FDIM];  // 2048 floats = 8 KB
    for (int i = threadIdx.x; i < HEADS * 2 * FDIM; i += blockDim.x)
        sh_aa[i] = aa[i];
    __syncthreads();

    int warp = (blockIdx.x * blockDim.x + threadIdx.x) >> 5;
    int lane = threadIdx.x & 31;
    if (warp >= n_nodes) return;

    // Each lane owns 4 consecutive features: coalesced float4 load of x row.
    float4 xv = reinterpret_cast<const float4*>(x + (size_t)warp * FDIM)[lane];

    float acc[16];
#pragma unroll
    for (int h = 0; h < HEADS; h++) {
        float4 as = reinterpret_cast<const float4*>(sh_aa + h * 2 * FDIM)[lane];
        float4 ad = reinterpret_cast<const float4*>(sh_aa + h * 2 * FDIM + FDIM)[lane];
        acc[h]         = xv.x * as.x + xv.y * as.y + xv.z * as.z + xv.w * as.w;
        acc[HEADS + h] = xv.x * ad.x + xv.y * ad.y + xv.z * ad.z + xv.w * ad.w;
    }

    // Butterfly reduce all 16 accumulators across the warp.
#pragma unroll
    for (int off = 16; off > 0; off >>= 1) {
#pragma unroll
        for (int i = 0; i < 16; i++)
            acc[i] += __shfl_xor_sync(0xffffffffu, acc[i], off);
    }

    if (lane < 16)
        g_sc[(size_t)warp * 16 + lane] = acc[lane];
    else if (lane < 24)
        g_ssum[(size_t)warp * 8 + (lane - 16)] = 0.0f;
}

// ---------------------------------------------------------------------------
// Per-edge score recompute helper: e = lrelu(s_src[r][h] + s_dst[c][h]);
// ex = exp(e). Identical instruction sequence in sum & out kernels so the
// numerator and denominator terms match bitwise.
// ---------------------------------------------------------------------------
__device__ __forceinline__ void edge_exp(int r, int c, float4& ex0, float4& ex1)
{
    const float4* sc4 = reinterpret_cast<const float4*>(g_sc);
    float4 a0 = __ldg(&sc4[(size_t)r * 4 + 0]);
    float4 a1 = __ldg(&sc4[(size_t)r * 4 + 1]);
    float4 b0 = __ldg(&sc4[(size_t)c * 4 + 2]);
    float4 b1 = __ldg(&sc4[(size_t)c * 4 + 3]);

    float e0x = a0.x + b0.x, e0y = a0.y + b0.y, e0z = a0.z + b0.z, e0w = a0.w + b0.w;
    float e1x = a1.x + b1.x, e1y = a1.y + b1.y, e1z = a1.z + b1.z, e1w = a1.w + b1.w;

    // leaky relu: max(e, alpha*e) is exact for alpha in (0,1)
    e0x = fmaxf(e0x, ALPHA_F * e0x); e0y = fmaxf(e0y, ALPHA_F * e0y);
    e0z = fmaxf(e0z, ALPHA_F * e0z); e0w = fmaxf(e0w, ALPHA_F * e0w);
    e1x = fmaxf(e1x, ALPHA_F * e1x); e1y = fmaxf(e1y, ALPHA_F * e1y);
    e1z = fmaxf(e1z, ALPHA_F * e1z); e1w = fmaxf(e1w, ALPHA_F * e1w);

    ex0 = make_float4(__expf(e0x), __expf(e0y), __expf(e0z), __expf(e0w));
    ex1 = make_float4(__expf(e1x), __expf(e1y), __expf(e1z), __expf(e1w));
}

// ---------------------------------------------------------------------------
// Kernel 2: segment-sum of exp(e) into g_ssum via vectorized L2 reductions.
// ---------------------------------------------------------------------------
__global__ void sum_kernel(const int* __restrict__ row,
                           const int* __restrict__ col,
                           int n_edges)
{
    int e = blockIdx.x * blockDim.x + threadIdx.x;
    if (e >= n_edges) return;
    int r = __ldg(row + e);
    int c = __ldg(col + e);

    float4 ex0, ex1;
    edge_exp(r, c, ex0, ex1);

    float* dst = g_ssum + (size_t)r * 8;
    asm volatile("red.global.add.v4.f32 [%0], {%1,%2,%3,%4};"
                 :: "l"(dst),     "f"(ex0.x), "f"(ex0.y), "f"(ex0.z), "f"(ex0.w)
                 : "memory");
    asm volatile("red.global.add.v4.f32 [%0], {%1,%2,%3,%4};"
                 :: "l"(dst + 4), "f"(ex1.x), "f"(ex1.y), "f"(ex1.z), "f"(ex1.w)
                 : "memory");
}

// ---------------------------------------------------------------------------
// Kernel 3: a[h][e] = exp(e)/(ssum[row][h] + EPS), transposed write.
// Per warp: 8 coalesced 128B output streams (one per head).
// ---------------------------------------------------------------------------
__global__ void out_kernel(const int* __restrict__ row,
                           const int* __restrict__ col,
                           float* __restrict__ out,
                           int n_edges)
{
    int e = blockIdx.x * blockDim.x + threadIdx.x;
    if (e >= n_edges) return;
    int r = __ldg(row + e);
    int c = __ldg(col + e);

    float4 ex0, ex1;
    edge_exp(r, c, ex0, ex1);

    const float4* ss4 = reinterpret_cast<const float4*>(g_ssum);
    float4 s0 = __ldg(&ss4[(size_t)r * 2 + 0]);
    float4 s1 = __ldg(&ss4[(size_t)r * 2 + 1]);

    size_t E = (size_t)n_edges;
    out[0 * E + e] = ex0.x * __frcp_rn(s0.x + EPS_F);
    out[1 * E + e] = ex0.y * __frcp_rn(s0.y + EPS_F);
    out[2 * E + e] = ex0.z * __frcp_rn(s0.z + EPS_F);
    out[3 * E + e] = ex0.w * __frcp_rn(s0.w + EPS_F);
    out[4 * E + e] = ex1.x * __frcp_rn(s1.x + EPS_F);
    out[5 * E + e] = ex1.y * __frcp_rn(s1.y + EPS_F);
    out[6 * E + e] = ex1.z * __frcp_rn(s1.z + EPS_F);
    out[7 * E + e] = ex1.w * __frcp_rn(s1.w + EPS_F);
}

extern "C" void kernel_launch(void* const* d_in, const int* in_sizes, int n_in,
                              void* d_out, int out_size)
{
    const float* x   = (const float*)d_in[0];
    const int*   row = (const int*)  d_in[1];
    const int*   col = (const int*)  d_in[2];
    const float* aa  = (const float*)d_in[3];
    float* out = (float*)d_out;

    int n_nodes = in_sizes[0] / FDIM;   // 100000
    int n_edges = in_sizes[1];          // 1600000

    // K1: one warp per node (also zeroes g_ssum)
    {
        int threads = 256;
        int warps_per_block = threads / 32;
        int blocks = (n_nodes + warps_per_block - 1) / warps_per_block;
        scores_kernel<<<blocks, threads>>>(x, aa, n_nodes);
    }
    // K2: segment-sum of exp
    {
        int threads = 256;
        int blocks = (n_edges + threads - 1) / threads;
        sum_kernel<<<blocks, threads>>>(row, col, n_edges);
    }
    // K3: normalize + transposed write
    {
        int threads = 256;
        int blocks = (n_edges + threads - 1) / threads;
        out_kernel<<<blocks, threads>>>(row, col, out, n_edges);
    }
}